// round 1
// baseline (speedup 1.0000x reference)
#include <cuda_runtime.h>
#include <math.h>

#define NMAX 65536
#define EMAX 1048576
#define GMAXG 1024
#define DD 128
#define EFD 8
#define NLAYERS 4

// ---------------- static device scratch (no allocation allowed) ----------------
__device__ float g_x0[NMAX * DD];
__device__ float g_x1[NMAX * DD];
__device__ float g_xl[NMAX * DD];
__device__ float g_xr[NMAX * DD];
__device__ float g_loop_raw[NMAX * EFD];
__device__ int   g_deg[NMAX + 1];
__device__ int   g_rowoff[NMAX + 1];
__device__ int   g_cursor[NMAX];
__device__ int   g_csr_src[EMAX];
__device__ float g_csr_attr[EMAX * EFD];
__device__ float g_M[NLAYERS * EFD * DD];   // edge_W @ We[l]
__device__ float g_cv[NLAYERS * DD];        // edge_b @ We[l]
__device__ float g_gsum[GMAXG * DD];
__device__ int   g_gcnt[GMAXG];

// ---------------- helpers ----------------
__device__ __forceinline__ float lrelu(float x) { return x > 0.f ? x : 0.2f * x; }
__device__ __forceinline__ float quadsum(float v) {
    v += __shfl_xor_sync(0xffffffffu, v, 1);
    v += __shfl_xor_sync(0xffffffffu, v, 2);
    return v;
}

// ---------------- kernels ----------------
__global__ void zero_kernel(int N, int G) {
    int i = blockIdx.x * blockDim.x + threadIdx.x;
    if (i < N * EFD) g_loop_raw[i] = 0.f;
    if (i <= N) g_deg[i] = 0;
    if (i < N) g_cursor[i] = 0;
    if (i < G * DD) g_gsum[i] = 0.f;
    if (i < G) g_gcnt[i] = 0;
}

__global__ void encode_kernel(const int* __restrict__ x_nodes,
                              const float* __restrict__ node_emb, int N) {
    int i = blockIdx.x * blockDim.x + threadIdx.x;
    if (i >= N * 32) return;
    int n = i >> 5, q = i & 31;
    int cat = x_nodes[n];
    float4 v = *(const float4*)(node_emb + cat * DD + q * 4);
    *(float4*)(g_x0 + n * DD + q * 4) = v;
}

__global__ void pass1_kernel(const int* __restrict__ src, const int* __restrict__ dst,
                             const float* __restrict__ ea, int E) {
    int e = blockIdx.x * blockDim.x + threadIdx.x;
    if (e >= E) return;
    int s = src[e], d = dst[e];
    if (s == d) return;  // masked self-edges contribute nothing anywhere
    atomicAdd(&g_deg[d], 1);
#pragma unroll
    for (int f = 0; f < EFD; f++) atomicAdd(&g_loop_raw[d * EFD + f], ea[e * EFD + f]);
}

__global__ void scan_kernel(int N) {
    __shared__ int ssum[1024];
    int t = threadIdx.x;
    int chunk = (N + 1023) >> 10;
    int beg = t * chunk;
    int end = min(beg + chunk, N);
    int s = 0;
    for (int i = beg; i < end; i++) s += g_deg[i];
    ssum[t] = s;
    __syncthreads();
    for (int off = 1; off < 1024; off <<= 1) {
        int v = (t >= off) ? ssum[t - off] : 0;
        __syncthreads();
        ssum[t] += v;
        __syncthreads();
    }
    int run = (t == 0) ? 0 : ssum[t - 1];
    for (int i = beg; i < end; i++) { g_rowoff[i] = run; run += g_deg[i]; }
    if (beg < N && end == N) g_rowoff[N] = run;
}

__global__ void scatter_kernel(const int* __restrict__ src, const int* __restrict__ dst,
                               const float* __restrict__ ea, int E) {
    int e = blockIdx.x * blockDim.x + threadIdx.x;
    if (e >= E) return;
    int s = src[e], d = dst[e];
    if (s == d) return;
    int pos = g_rowoff[d] + atomicAdd(&g_cursor[d], 1);
    g_csr_src[pos] = s;
    float4 a0 = *(const float4*)(ea + e * EFD);
    float4 a1 = *(const float4*)(ea + e * EFD + 4);
    *(float4*)(g_csr_attr + pos * EFD) = a0;
    *(float4*)(g_csr_attr + pos * EFD + 4) = a1;
}

__global__ void prep_kernel(const float* __restrict__ edge_W,
                            const float* __restrict__ edge_b,
                            const float* __restrict__ We) {
    int idx = blockIdx.x * blockDim.x + threadIdx.x;
    if (idx < NLAYERS * EFD * DD) {
        int l = idx / (EFD * DD);
        int rem = idx % (EFD * DD);
        int f = rem / DD, j = rem % DD;
        const float* WeL = We + l * 64 * DD;
        float s = 0.f;
        for (int k = 0; k < 64; k++) s = fmaf(edge_W[f * 64 + k], WeL[k * DD + j], s);
        g_M[idx] = s;
    } else if (idx < NLAYERS * EFD * DD + NLAYERS * DD) {
        int t = idx - NLAYERS * EFD * DD;
        int l = t / DD, j = t % DD;
        const float* WeL = We + l * 64 * DD;
        float s = 0.f;
        for (int k = 0; k < 64; k++) s = fmaf(edge_b[k], WeL[k * DD + j], s);
        g_cv[t] = s;
    }
}

// xl = x @ Wl + bl, xr = x @ Wr + br  (blockIdx.y picks which)
__global__ void gemm_kernel(int pin,
                            const float* __restrict__ Wl, const float* __restrict__ bl,
                            const float* __restrict__ Wr, const float* __restrict__ br,
                            int N) {
    const float* A = pin ? g_x1 : g_x0;
    const float* W; const float* bias; float* Out;
    if (blockIdx.y == 0) { W = Wl; bias = bl; Out = g_xl; }
    else { W = Wr; bias = br; Out = g_xr; }

    __shared__ float As[128][64];   // [k][row] transposed, 32 KB
    int tid = threadIdx.x;
    int rowbase = blockIdx.x * 64;

    for (int i = tid; i < 64 * 32; i += 256) {
        int r = i & 63, kq = i >> 6;
        int row = rowbase + r;
        float4 v = make_float4(0.f, 0.f, 0.f, 0.f);
        if (row < N) v = *(const float4*)(A + row * DD + kq * 4);
        As[kq * 4 + 0][r] = v.x;
        As[kq * 4 + 1][r] = v.y;
        As[kq * 4 + 2][r] = v.z;
        As[kq * 4 + 3][r] = v.w;
    }
    __syncthreads();

    int tx = tid & 15, ty = tid >> 4;   // 16 x 16 threads; thread tile = 4 rows x 8 cols
    float acc[4][8];
#pragma unroll
    for (int r = 0; r < 4; r++)
#pragma unroll
        for (int j = 0; j < 8; j++) acc[r][j] = 0.f;

#pragma unroll 8
    for (int k = 0; k < 128; k++) {
        float4 a = *(const float4*)(&As[k][ty * 4]);
        const float4* wr = (const float4*)(W + k * DD + tx * 8);
        float4 b0 = __ldg(wr);
        float4 b1 = __ldg(wr + 1);
        float av[4] = {a.x, a.y, a.z, a.w};
        float bv[8] = {b0.x, b0.y, b0.z, b0.w, b1.x, b1.y, b1.z, b1.w};
#pragma unroll
        for (int r = 0; r < 4; r++)
#pragma unroll
            for (int j = 0; j < 8; j++) acc[r][j] = fmaf(av[r], bv[j], acc[r][j]);
    }

    float bs[8];
#pragma unroll
    for (int j = 0; j < 8; j++) bs[j] = bias[tx * 8 + j];
#pragma unroll
    for (int r = 0; r < 4; r++) {
        int row = rowbase + ty * 4 + r;
        if (row < N) {
            float4 o0 = make_float4(acc[r][0] + bs[0], acc[r][1] + bs[1],
                                    acc[r][2] + bs[2], acc[r][3] + bs[3]);
            float4 o1 = make_float4(acc[r][4] + bs[4], acc[r][5] + bs[5],
                                    acc[r][6] + bs[6], acc[r][7] + bs[7]);
            *(float4*)(Out + row * DD + tx * 8) = o0;
            *(float4*)(Out + row * DD + tx * 8 + 4) = o1;
        }
    }
}

#define EPADD(sc, mv) { e.x = fmaf((sc), (mv).x, e.x); e.y = fmaf((sc), (mv).y, e.y); \
                        e.z = fmaf((sc), (mv).z, e.z); e.w = fmaf((sc), (mv).w, e.w); }

// one warp per destination node; streaming (online) segment softmax + aggregation
__global__ void attn_kernel(int layer, int pout, int N,
                            const float* __restrict__ att, const float* __restrict__ gbias,
                            const float* __restrict__ gamma, const float* __restrict__ beta) {
    int w = (blockIdx.x * blockDim.x + threadIdx.x) >> 5;
    int lane = threadIdx.x & 31;
    if (w >= N) return;
    int n = w;
    float* xout = pout ? g_x1 : g_x0;

    const float4* Mbase = (const float4*)(g_M + layer * EFD * DD);
    float4 Mv[8];
#pragma unroll
    for (int f = 0; f < 8; f++) Mv[f] = Mbase[f * 32 + lane];
    float4 cv = ((const float4*)(g_cv + layer * DD))[lane];
    float4 av = ((const float4*)att)[lane];
    float4 xr = ((const float4*)g_xr)[n * 32 + lane];
    float4 xls = ((const float4*)g_xl)[n * 32 + lane];

    // self-loop edge feature: mean of raw incoming attrs through M (0 if no edges)
    int cnt = g_deg[n];
    float4 e;
    if (cnt > 0) {
        float inv = 1.f / (float)cnt;
        float4 a0 = *(const float4*)(g_loop_raw + n * EFD);
        float4 a1 = *(const float4*)(g_loop_raw + n * EFD + 4);
        e = cv;
        EPADD(a0.x * inv, Mv[0]); EPADD(a0.y * inv, Mv[1]);
        EPADD(a0.z * inv, Mv[2]); EPADD(a0.w * inv, Mv[3]);
        EPADD(a1.x * inv, Mv[4]); EPADD(a1.y * inv, Mv[5]);
        EPADD(a1.z * inv, Mv[6]); EPADD(a1.w * inv, Mv[7]);
    } else {
        e = make_float4(0.f, 0.f, 0.f, 0.f);
    }

    // self-loop logit
    float p0 = lrelu(xls.x + xr.x + e.x) * av.x;
    p0 = fmaf(lrelu(xls.y + xr.y + e.y), av.y, p0);
    p0 = fmaf(lrelu(xls.z + xr.z + e.z), av.z, p0);
    p0 = fmaf(lrelu(xls.w + xr.w + e.w), av.w, p0);
    float m = quadsum(p0);
    float denom = 1.f;
    float4 acc = xls;

    int beg = g_rowoff[n], end = g_rowoff[n + 1];
    for (int k = beg; k < end; k++) {
        int s = g_csr_src[k];
        float4 a0 = *(const float4*)(g_csr_attr + k * EFD);
        float4 a1 = *(const float4*)(g_csr_attr + k * EFD + 4);
        float4 xv = ((const float4*)g_xl)[s * 32 + lane];
        e = cv;
        EPADD(a0.x, Mv[0]); EPADD(a0.y, Mv[1]); EPADD(a0.z, Mv[2]); EPADD(a0.w, Mv[3]);
        EPADD(a1.x, Mv[4]); EPADD(a1.y, Mv[5]); EPADD(a1.z, Mv[6]); EPADD(a1.w, Mv[7]);
        float pt = lrelu(xv.x + xr.x + e.x) * av.x;
        pt = fmaf(lrelu(xv.y + xr.y + e.y), av.y, pt);
        pt = fmaf(lrelu(xv.z + xr.z + e.z), av.z, pt);
        pt = fmaf(lrelu(xv.w + xr.w + e.w), av.w, pt);
        float lg = quadsum(pt);
        float nm = fmaxf(m, lg);
        float sc = __expf(m - nm);
        float p = __expf(lg - nm);
        denom = fmaf(denom, sc, p);
        acc.x = fmaf(acc.x, sc, p * xv.x);
        acc.y = fmaf(acc.y, sc, p * xv.y);
        acc.z = fmaf(acc.z, sc, p * xv.z);
        acc.w = fmaf(acc.w, sc, p * xv.w);
        m = nm;
    }

    float inv = 1.f / denom;
    float4 gb = ((const float4*)gbias)[lane];
    float4 gm = ((const float4*)gamma)[lane];
    float4 bt = ((const float4*)beta)[lane];
    const float BNS = rsqrtf(1.f + 1e-5f);
    float hx = fmaf(gm.x * BNS, fmaf(acc.x, inv, gb.x), bt.x);
    float hy = fmaf(gm.y * BNS, fmaf(acc.y, inv, gb.y), bt.y);
    float hz = fmaf(gm.z * BNS, fmaf(acc.z, inv, gb.z), bt.z);
    float hw = fmaf(gm.w * BNS, fmaf(acc.w, inv, gb.w), bt.w);
    float4 o;
    o.x = hx > 0.f ? hx : expm1f(hx);
    o.y = hy > 0.f ? hy : expm1f(hy);
    o.z = hz > 0.f ? hz : expm1f(hz);
    o.w = hw > 0.f ? hw : expm1f(hw);
    ((float4*)xout)[n * 32 + lane] = o;
}

__global__ void pool_kernel(const int* __restrict__ batch, int pin, int N) {
    int i = blockIdx.x * blockDim.x + threadIdx.x;
    if (i >= N * 32) return;
    int n = i >> 5, q = i & 31;
    const float* x = pin ? g_x1 : g_x0;
    float4 v = ((const float4*)x)[n * 32 + q];
    int g = batch[n];
    atomicAdd(&g_gsum[g * DD + q * 4 + 0], v.x);
    atomicAdd(&g_gsum[g * DD + q * 4 + 1], v.y);
    atomicAdd(&g_gsum[g * DD + q * 4 + 2], v.z);
    atomicAdd(&g_gsum[g * DD + q * 4 + 3], v.w);
    if (q == 0) atomicAdd(&g_gcnt[g], 1);
}

__global__ void head_kernel(const float* __restrict__ hW, const float* __restrict__ hb,
                            float* __restrict__ out, int G) {
    __shared__ float sh[DD];
    int g = blockIdx.x;
    int c = threadIdx.x;
    float cntf = (float)max(g_gcnt[g], 1);
    sh[c] = g_gsum[g * DD + c] / cntf;
    __syncthreads();
    if (c < 10) {
        float s = hb[c];
#pragma unroll 16
        for (int k = 0; k < DD; k++) s = fmaf(sh[k], hW[k * 10 + c], s);
        out[g * 10 + c] = s;
    }
}

// ---------------- launch ----------------
extern "C" void kernel_launch(void* const* d_in, const int* in_sizes, int n_in,
                              void* d_out, int out_size) {
    const int*   x_nodes  = (const int*)d_in[0];
    const int*   esrc     = (const int*)d_in[1];
    const int*   edst     = (const int*)d_in[2];
    const float* eattr    = (const float*)d_in[3];
    const int*   batch    = (const int*)d_in[4];
    const float* node_emb = (const float*)d_in[5];
    const float* edge_W   = (const float*)d_in[6];
    const float* edge_b   = (const float*)d_in[7];
    const float* Wl       = (const float*)d_in[8];
    const float* bl       = (const float*)d_in[9];
    const float* Wr       = (const float*)d_in[10];
    const float* br       = (const float*)d_in[11];
    const float* We       = (const float*)d_in[12];
    const float* att      = (const float*)d_in[13];
    const float* gbias    = (const float*)d_in[14];
    const float* gamma    = (const float*)d_in[15];
    const float* beta     = (const float*)d_in[16];
    const float* headW    = (const float*)d_in[17];
    const float* headb    = (const float*)d_in[18];
    float* out = (float*)d_out;

    int N = in_sizes[0];
    int E = in_sizes[1];
    int G = out_size / 10;

    int zT = N * EFD;
    if (G * DD > zT) zT = G * DD;
    zT += 1;
    zero_kernel<<<(zT + 255) / 256, 256>>>(N, G);
    encode_kernel<<<(N * 32 + 255) / 256, 256>>>(x_nodes, node_emb, N);
    pass1_kernel<<<(E + 255) / 256, 256>>>(esrc, edst, eattr, E);
    scan_kernel<<<1, 1024>>>(N);
    scatter_kernel<<<(E + 255) / 256, 256>>>(esrc, edst, eattr, E);
    prep_kernel<<<(NLAYERS * EFD * DD + NLAYERS * DD + 255) / 256, 256>>>(edge_W, edge_b, We);

    int pin = 0;
    for (int l = 0; l < NLAYERS; l++) {
        dim3 gg((N + 63) / 64, 2);
        gemm_kernel<<<gg, 256>>>(pin, Wl + l * DD * DD, bl + l * DD,
                                 Wr + l * DD * DD, br + l * DD, N);
        attn_kernel<<<(N * 32 + 255) / 256, 256>>>(l, 1 - pin, N,
                                                   att + l * DD, gbias + l * DD,
                                                   gamma + l * DD, beta + l * DD);
        pin = 1 - pin;
    }

    pool_kernel<<<(N * 32 + 255) / 256, 256>>>(batch, pin, N);
    head_kernel<<<G, 128>>>(headW, headb, out, G);
}

// round 2
// speedup vs baseline: 1.1666x; 1.1666x over previous
#include <cuda_runtime.h>
#include <math.h>

#define NMAX 65536
#define EMAX 1048576
#define GMAXG 1024
#define DD 128
#define EFD 8
#define NLAYERS 4
#define SCAN_BS 256

// ---------------- static device scratch (no allocation allowed) ----------------
__device__ float g_x0[NMAX * DD];
__device__ float g_x1[NMAX * DD];
__device__ float g_xl[NMAX * DD];
__device__ float g_xr[NMAX * DD];
__device__ float g_loop_raw[NMAX * EFD];
__device__ int   g_deg[NMAX + 1];
__device__ int   g_rowoff[NMAX + 1];
__device__ int   g_cursor[NMAX];
__device__ int   g_bsum[NMAX / SCAN_BS + 1];
__device__ int   g_boff[NMAX / SCAN_BS + 2];
__device__ int   g_csr_src[EMAX];
__device__ float g_csr_attr[EMAX * EFD];
__device__ float g_M[NLAYERS * EFD * DD];   // edge_W @ We[l]
__device__ float g_cv[NLAYERS * DD];        // edge_b @ We[l]
__device__ float g_gsum[GMAXG * DD];
__device__ int   g_gcnt[GMAXG];

// ---------------- helpers ----------------
typedef unsigned long long ull;

__device__ __forceinline__ float lrelu(float x) { return x > 0.f ? x : 0.2f * x; }
__device__ __forceinline__ float quadsum(float v) {
    v += __shfl_xor_sync(0xffffffffu, v, 1);
    v += __shfl_xor_sync(0xffffffffu, v, 2);
    return v;
}
__device__ __forceinline__ ull pack2(float lo, float hi) {
    ull r; asm("mov.b64 %0, {%1, %2};" : "=l"(r) : "f"(lo), "f"(hi)); return r;
}
__device__ __forceinline__ float2 unpack2(ull v) {
    float2 r; asm("mov.b64 {%0, %1}, %2;" : "=f"(r.x), "=f"(r.y) : "l"(v)); return r;
}
__device__ __forceinline__ void ffma2(ull& d, ull a, ull b) {
    asm("fma.rn.f32x2 %0, %1, %2, %0;" : "+l"(d) : "l"(a), "l"(b));
}
__device__ __forceinline__ void redg4(float* p, float4 v) {
    asm volatile("red.global.add.v4.f32 [%0], {%1, %2, %3, %4};"
                 :: "l"(p), "f"(v.x), "f"(v.y), "f"(v.z), "f"(v.w) : "memory");
}

// ---------------- kernels ----------------
__global__ void zero_kernel(int N, int G) {
    int i = blockIdx.x * blockDim.x + threadIdx.x;
    if (i < N * EFD) g_loop_raw[i] = 0.f;
    if (i <= N) g_deg[i] = 0;
    if (i < N) g_cursor[i] = 0;
    if (i < G * DD) g_gsum[i] = 0.f;
    if (i < G) g_gcnt[i] = 0;
}

__global__ void encode_kernel(const int* __restrict__ x_nodes,
                              const float* __restrict__ node_emb, int N) {
    int i = blockIdx.x * blockDim.x + threadIdx.x;
    if (i >= N * 32) return;
    int n = i >> 5, q = i & 31;
    int cat = x_nodes[n];
    float4 v = *(const float4*)(node_emb + cat * DD + q * 4);
    *(float4*)(g_x0 + n * DD + q * 4) = v;
}

__global__ void pass1_kernel(const int* __restrict__ src, const int* __restrict__ dst,
                             const float* __restrict__ ea, int E) {
    int e = blockIdx.x * blockDim.x + threadIdx.x;
    if (e >= E) return;
    int s = src[e], d = dst[e];
    if (s == d) return;  // masked self-edges contribute nothing anywhere
    atomicAdd(&g_deg[d], 1);
    float4 a0 = *(const float4*)(ea + e * EFD);
    float4 a1 = *(const float4*)(ea + e * EFD + 4);
    redg4(&g_loop_raw[d * EFD], a0);
    redg4(&g_loop_raw[d * EFD + 4], a1);
}

// --- 3-kernel multi-block exclusive scan of g_deg[0..N) -> g_rowoff ---
__global__ void scan1_kernel(int N) {
    __shared__ int s[SCAN_BS];
    int b = blockIdx.x, t = threadIdx.x;
    int i = b * SCAN_BS + t;
    int v = (i < N) ? g_deg[i] : 0;
    s[t] = v;
    __syncthreads();
#pragma unroll
    for (int off = 1; off < SCAN_BS; off <<= 1) {
        int u = (t >= off) ? s[t - off] : 0;
        __syncthreads();
        s[t] += u;
        __syncthreads();
    }
    if (i < N) g_rowoff[i] = (t == 0) ? 0 : s[t - 1];
    if (t == SCAN_BS - 1) g_bsum[b] = s[t];
}

__global__ void scan2_kernel(int nb) {
    __shared__ int s[SCAN_BS];
    int t = threadIdx.x;
    int v = (t < nb) ? g_bsum[t] : 0;
    s[t] = v;
    __syncthreads();
#pragma unroll
    for (int off = 1; off < SCAN_BS; off <<= 1) {
        int u = (t >= off) ? s[t - off] : 0;
        __syncthreads();
        s[t] += u;
        __syncthreads();
    }
    g_boff[t] = (t == 0) ? 0 : s[t - 1];
    if (t == SCAN_BS - 1) g_boff[SCAN_BS] = s[t];
}

__global__ void scan3_kernel(int N, int nb) {
    int i = blockIdx.x * blockDim.x + threadIdx.x;
    if (i < N) g_rowoff[i] += g_boff[i / SCAN_BS];
    if (i == 0) g_rowoff[N] = g_boff[nb];
}

__global__ void scatter_kernel(const int* __restrict__ src, const int* __restrict__ dst,
                               const float* __restrict__ ea, int E) {
    int e = blockIdx.x * blockDim.x + threadIdx.x;
    if (e >= E) return;
    int s = src[e], d = dst[e];
    if (s == d) return;
    int pos = g_rowoff[d] + atomicAdd(&g_cursor[d], 1);
    g_csr_src[pos] = s;
    float4 a0 = *(const float4*)(ea + e * EFD);
    float4 a1 = *(const float4*)(ea + e * EFD + 4);
    *(float4*)(g_csr_attr + pos * EFD) = a0;
    *(float4*)(g_csr_attr + pos * EFD + 4) = a1;
}

__global__ void prep_kernel(const float* __restrict__ edge_W,
                            const float* __restrict__ edge_b,
                            const float* __restrict__ We) {
    int idx = blockIdx.x * blockDim.x + threadIdx.x;
    if (idx < NLAYERS * EFD * DD) {
        int l = idx / (EFD * DD);
        int rem = idx % (EFD * DD);
        int f = rem / DD, j = rem % DD;
        const float* WeL = We + l * 64 * DD;
        float s = 0.f;
        for (int k = 0; k < 64; k++) s = fmaf(edge_W[f * 64 + k], WeL[k * DD + j], s);
        g_M[idx] = s;
    } else if (idx < NLAYERS * EFD * DD + NLAYERS * DD) {
        int t = idx - NLAYERS * EFD * DD;
        int l = t / DD, j = t % DD;
        const float* WeL = We + l * 64 * DD;
        float s = 0.f;
        for (int k = 0; k < 64; k++) s = fmaf(edge_b[k], WeL[k * DD + j], s);
        g_cv[t] = s;
    }
}

// xl = x @ Wl + bl, xr = x @ Wr + br  (blockIdx.y picks which)
// inner loop uses packed fp32x2 FFMA (2x FFMA throughput, full fp32 precision)
__global__ void gemm_kernel(int pin,
                            const float* __restrict__ Wl, const float* __restrict__ bl,
                            const float* __restrict__ Wr, const float* __restrict__ br,
                            int N) {
    const float* A = pin ? g_x1 : g_x0;
    const float* W; const float* bias; float* Out;
    if (blockIdx.y == 0) { W = Wl; bias = bl; Out = g_xl; }
    else { W = Wr; bias = br; Out = g_xr; }

    __shared__ float As[128][64];   // [k][row] transposed, 32 KB
    int tid = threadIdx.x;
    int rowbase = blockIdx.x * 64;

    for (int i = tid; i < 64 * 32; i += 256) {
        int r = i & 63, kq = i >> 6;
        int row = rowbase + r;
        float4 v = make_float4(0.f, 0.f, 0.f, 0.f);
        if (row < N) v = *(const float4*)(A + row * DD + kq * 4);
        As[kq * 4 + 0][r] = v.x;
        As[kq * 4 + 1][r] = v.y;
        As[kq * 4 + 2][r] = v.z;
        As[kq * 4 + 3][r] = v.w;
    }
    __syncthreads();

    int tx = tid & 15, ty = tid >> 4;   // 16 x 16 threads; thread tile = 4 rows x 8 cols
    ull acc2[4][4];
    ull zz = pack2(0.f, 0.f);
#pragma unroll
    for (int r = 0; r < 4; r++)
#pragma unroll
        for (int j = 0; j < 4; j++) acc2[r][j] = zz;

#pragma unroll 4
    for (int k = 0; k < 128; k++) {
        float4 a = *(const float4*)(&As[k][ty * 4]);
        const ulonglong2* wr = (const ulonglong2*)(W + k * DD + tx * 8);
        ulonglong2 w0 = wr[0];        // (b0,b1) (b2,b3)
        ulonglong2 w1 = wr[1];        // (b4,b5) (b6,b7)
        ull ap0 = pack2(a.x, a.x);
        ull ap1 = pack2(a.y, a.y);
        ull ap2 = pack2(a.z, a.z);
        ull ap3 = pack2(a.w, a.w);
        ffma2(acc2[0][0], ap0, w0.x); ffma2(acc2[0][1], ap0, w0.y);
        ffma2(acc2[0][2], ap0, w1.x); ffma2(acc2[0][3], ap0, w1.y);
        ffma2(acc2[1][0], ap1, w0.x); ffma2(acc2[1][1], ap1, w0.y);
        ffma2(acc2[1][2], ap1, w1.x); ffma2(acc2[1][3], ap1, w1.y);
        ffma2(acc2[2][0], ap2, w0.x); ffma2(acc2[2][1], ap2, w0.y);
        ffma2(acc2[2][2], ap2, w1.x); ffma2(acc2[2][3], ap2, w1.y);
        ffma2(acc2[3][0], ap3, w0.x); ffma2(acc2[3][1], ap3, w0.y);
        ffma2(acc2[3][2], ap3, w1.x); ffma2(acc2[3][3], ap3, w1.y);
    }

    float bs[8];
#pragma unroll
    for (int j = 0; j < 8; j++) bs[j] = bias[tx * 8 + j];
#pragma unroll
    for (int r = 0; r < 4; r++) {
        int row = rowbase + ty * 4 + r;
        if (row < N) {
            float2 p0 = unpack2(acc2[r][0]);
            float2 p1 = unpack2(acc2[r][1]);
            float2 p2 = unpack2(acc2[r][2]);
            float2 p3 = unpack2(acc2[r][3]);
            float4 o0 = make_float4(p0.x + bs[0], p0.y + bs[1], p1.x + bs[2], p1.y + bs[3]);
            float4 o1 = make_float4(p2.x + bs[4], p2.y + bs[5], p3.x + bs[6], p3.y + bs[7]);
            *(float4*)(Out + row * DD + tx * 8) = o0;
            *(float4*)(Out + row * DD + tx * 8 + 4) = o1;
        }
    }
}

// one warp per destination node; streaming (online) segment softmax + aggregation
__global__ void attn_kernel(int layer, int pout, int N,
                            const float* __restrict__ att, const float* __restrict__ gbias,
                            const float* __restrict__ gamma, const float* __restrict__ beta) {
    int w = (blockIdx.x * blockDim.x + threadIdx.x) >> 5;
    int lane = threadIdx.x & 31;
    if (w >= N) return;
    int n = w;
    float* xout = pout ? g_x1 : g_x0;

    const float4* Mbase = (const float4*)(g_M + layer * EFD * DD);
    ull Mp[8][2];
#pragma unroll
    for (int f = 0; f < 8; f++) {
        float4 mv = Mbase[f * 32 + lane];
        Mp[f][0] = pack2(mv.x, mv.y);
        Mp[f][1] = pack2(mv.z, mv.w);
    }
    float4 cv = ((const float4*)(g_cv + layer * DD))[lane];
    ull cvp0 = pack2(cv.x, cv.y), cvp1 = pack2(cv.z, cv.w);
    float4 av = ((const float4*)att)[lane];
    float4 xr = ((const float4*)g_xr)[n * 32 + lane];
    float4 xls = ((const float4*)g_xl)[n * 32 + lane];

    // self-loop edge feature: mean of raw incoming attrs through M (0 if no edges)
    int cnt = g_deg[n];
    float ex, ey, ez, ew;
    if (cnt > 0) {
        float inv = 1.f / (float)cnt;
        float4 a0 = *(const float4*)(g_loop_raw + n * EFD);
        float4 a1 = *(const float4*)(g_loop_raw + n * EFD + 4);
        ull e0 = cvp0, e1 = cvp1;
        float pa[8] = {a0.x * inv, a0.y * inv, a0.z * inv, a0.w * inv,
                       a1.x * inv, a1.y * inv, a1.z * inv, a1.w * inv};
#pragma unroll
        for (int f = 0; f < 8; f++) {
            ull sp = pack2(pa[f], pa[f]);
            ffma2(e0, sp, Mp[f][0]);
            ffma2(e1, sp, Mp[f][1]);
        }
        float2 eA = unpack2(e0), eB = unpack2(e1);
        ex = eA.x; ey = eA.y; ez = eB.x; ew = eB.y;
    } else {
        ex = ey = ez = ew = 0.f;
    }

    // self-loop logit
    float p0 = lrelu(xls.x + xr.x + ex) * av.x;
    p0 = fmaf(lrelu(xls.y + xr.y + ey), av.y, p0);
    p0 = fmaf(lrelu(xls.z + xr.z + ez), av.z, p0);
    p0 = fmaf(lrelu(xls.w + xr.w + ew), av.w, p0);
    float m = quadsum(p0);
    float denom = 1.f;
    float4 acc = xls;

    int beg = g_rowoff[n], end = g_rowoff[n + 1];
    for (int k = beg; k < end; k++) {
        int s = g_csr_src[k];
        float4 a0 = *(const float4*)(g_csr_attr + k * EFD);
        float4 a1 = *(const float4*)(g_csr_attr + k * EFD + 4);
        float4 xv = ((const float4*)g_xl)[s * 32 + lane];
        ull e0 = cvp0, e1 = cvp1;
        {
            ull sp;
            sp = pack2(a0.x, a0.x); ffma2(e0, sp, Mp[0][0]); ffma2(e1, sp, Mp[0][1]);
            sp = pack2(a0.y, a0.y); ffma2(e0, sp, Mp[1][0]); ffma2(e1, sp, Mp[1][1]);
            sp = pack2(a0.z, a0.z); ffma2(e0, sp, Mp[2][0]); ffma2(e1, sp, Mp[2][1]);
            sp = pack2(a0.w, a0.w); ffma2(e0, sp, Mp[3][0]); ffma2(e1, sp, Mp[3][1]);
            sp = pack2(a1.x, a1.x); ffma2(e0, sp, Mp[4][0]); ffma2(e1, sp, Mp[4][1]);
            sp = pack2(a1.y, a1.y); ffma2(e0, sp, Mp[5][0]); ffma2(e1, sp, Mp[5][1]);
            sp = pack2(a1.z, a1.z); ffma2(e0, sp, Mp[6][0]); ffma2(e1, sp, Mp[6][1]);
            sp = pack2(a1.w, a1.w); ffma2(e0, sp, Mp[7][0]); ffma2(e1, sp, Mp[7][1]);
        }
        float2 eA = unpack2(e0), eB = unpack2(e1);
        float pt = lrelu(xv.x + xr.x + eA.x) * av.x;
        pt = fmaf(lrelu(xv.y + xr.y + eA.y), av.y, pt);
        pt = fmaf(lrelu(xv.z + xr.z + eB.x), av.z, pt);
        pt = fmaf(lrelu(xv.w + xr.w + eB.y), av.w, pt);
        float lg = quadsum(pt);
        float nm = fmaxf(m, lg);
        float sc = __expf(m - nm);
        float p = __expf(lg - nm);
        denom = fmaf(denom, sc, p);
        acc.x = fmaf(acc.x, sc, p * xv.x);
        acc.y = fmaf(acc.y, sc, p * xv.y);
        acc.z = fmaf(acc.z, sc, p * xv.z);
        acc.w = fmaf(acc.w, sc, p * xv.w);
        m = nm;
    }

    float inv = 1.f / denom;
    float4 gb = ((const float4*)gbias)[lane];
    float4 gm = ((const float4*)gamma)[lane];
    float4 bt = ((const float4*)beta)[lane];
    const float BNS = rsqrtf(1.f + 1e-5f);
    float hx = fmaf(gm.x * BNS, fmaf(acc.x, inv, gb.x), bt.x);
    float hy = fmaf(gm.y * BNS, fmaf(acc.y, inv, gb.y), bt.y);
    float hz = fmaf(gm.z * BNS, fmaf(acc.z, inv, gb.z), bt.z);
    float hw = fmaf(gm.w * BNS, fmaf(acc.w, inv, gb.w), bt.w);
    float4 o;
    o.x = hx > 0.f ? hx : expm1f(hx);
    o.y = hy > 0.f ? hy : expm1f(hy);
    o.z = hz > 0.f ? hz : expm1f(hz);
    o.w = hw > 0.f ? hw : expm1f(hw);
    ((float4*)xout)[n * 32 + lane] = o;
}

__global__ void pool_kernel(const int* __restrict__ batch, int pin, int N) {
    int i = blockIdx.x * blockDim.x + threadIdx.x;
    if (i >= N * 32) return;
    int n = i >> 5, q = i & 31;
    const float* x = pin ? g_x1 : g_x0;
    float4 v = ((const float4*)x)[n * 32 + q];
    int g = batch[n];
    redg4(&g_gsum[g * DD + q * 4], v);
    if (q == 0) atomicAdd(&g_gcnt[g], 1);
}

__global__ void head_kernel(const float* __restrict__ hW, const float* __restrict__ hb,
                            float* __restrict__ out, int G) {
    __shared__ float sh[DD];
    int g = blockIdx.x;
    int c = threadIdx.x;
    float cntf = (float)max(g_gcnt[g], 1);
    sh[c] = g_gsum[g * DD + c] / cntf;
    __syncthreads();
    if (c < 10) {
        float s = hb[c];
#pragma unroll 16
        for (int k = 0; k < DD; k++) s = fmaf(sh[k], hW[k * 10 + c], s);
        out[g * 10 + c] = s;
    }
}

// ---------------- launch ----------------
extern "C" void kernel_launch(void* const* d_in, const int* in_sizes, int n_in,
                              void* d_out, int out_size) {
    const int*   x_nodes  = (const int*)d_in[0];
    const int*   esrc     = (const int*)d_in[1];
    const int*   edst     = (const int*)d_in[2];
    const float* eattr    = (const float*)d_in[3];
    const int*   batch    = (const int*)d_in[4];
    const float* node_emb = (const float*)d_in[5];
    const float* edge_W   = (const float*)d_in[6];
    const float* edge_b   = (const float*)d_in[7];
    const float* Wl       = (const float*)d_in[8];
    const float* bl       = (const float*)d_in[9];
    const float* Wr       = (const float*)d_in[10];
    const float* br       = (const float*)d_in[11];
    const float* We       = (const float*)d_in[12];
    const float* att      = (const float*)d_in[13];
    const float* gbias    = (const float*)d_in[14];
    const float* gamma    = (const float*)d_in[15];
    const float* beta     = (const float*)d_in[16];
    const float* headW    = (const float*)d_in[17];
    const float* headb    = (const float*)d_in[18];
    float* out = (float*)d_out;

    int N = in_sizes[0];
    int E = in_sizes[1];
    int G = out_size / 10;

    int zT = N * EFD;
    if (G * DD > zT) zT = G * DD;
    zT += 1;
    zero_kernel<<<(zT + 255) / 256, 256>>>(N, G);
    encode_kernel<<<(N * 32 + 255) / 256, 256>>>(x_nodes, node_emb, N);
    pass1_kernel<<<(E + 255) / 256, 256>>>(esrc, edst, eattr, E);

    int nb = (N + SCAN_BS - 1) / SCAN_BS;
    scan1_kernel<<<nb, SCAN_BS>>>(N);
    scan2_kernel<<<1, SCAN_BS>>>(nb);
    scan3_kernel<<<(N + 255) / 256, 256>>>(N, nb);

    scatter_kernel<<<(E + 255) / 256, 256>>>(esrc, edst, eattr, E);
    prep_kernel<<<(NLAYERS * EFD * DD + NLAYERS * DD + 255) / 256, 256>>>(edge_W, edge_b, We);

    int pin = 0;
    for (int l = 0; l < NLAYERS; l++) {
        dim3 gg((N + 63) / 64, 2);
        gemm_kernel<<<gg, 256>>>(pin, Wl + l * DD * DD, bl + l * DD,
                                 Wr + l * DD * DD, br + l * DD, N);
        attn_kernel<<<(N * 32 + 255) / 256, 256>>>(l, 1 - pin, N,
                                                   att + l * DD, gbias + l * DD,
                                                   gamma + l * DD, beta + l * DD);
        pin = 1 - pin;
    }

    pool_kernel<<<(N * 32 + 255) / 256, 256>>>(batch, pin, N);
    head_kernel<<<G, 128>>>(headW, headb, out, G);
}